// round 3
// baseline (speedup 1.0000x reference)
#include <cuda_runtime.h>
#include <math.h>
#include <stdint.h>

// Shapes: B=2, S=4096, H=1024, M=B*S=8192
#define BDIM 2
#define SDIM 4096
#define HDIM 1024
#define MDIM 8192

#define BM 128
#define BN 128
#define BK 16
#define AST 20    // smem row stride (floats) for [row][k] tiles, conflict-free
#define BKST 132  // smem row stride for [k][n] tile (NN B), conflict-free

// Scratch
__device__ float g_q[(size_t)MDIM * HDIM];
__device__ float g_k[(size_t)MDIM * HDIM];
__device__ float g_v[(size_t)MDIM * HDIM];
__device__ float g_attn[(size_t)MDIM * HDIM];
__device__ float g_s[(size_t)BDIM * SDIM * SDIM];

// ---------------- PTX helpers ----------------
__device__ __forceinline__ void split_tf32(float x, uint32_t& hi, uint32_t& lo) {
    uint32_t h;
    asm("cvt.rna.tf32.f32 %0, %1;" : "=r"(h) : "f"(x));
    float r = x - __uint_as_float(h);
    uint32_t l;
    asm("cvt.rna.tf32.f32 %0, %1;" : "=r"(l) : "f"(r));
    hi = h; lo = l;
}

__device__ __forceinline__ void mma_tf32(float* d, const uint32_t* a, const uint32_t* b) {
    asm volatile(
        "mma.sync.aligned.m16n8k8.row.col.f32.tf32.tf32.f32 "
        "{%0,%1,%2,%3}, {%4,%5,%6,%7}, {%8,%9}, {%0,%1,%2,%3};\n"
        : "+f"(d[0]), "+f"(d[1]), "+f"(d[2]), "+f"(d[3])
        : "r"(a[0]), "r"(a[1]), "r"(a[2]), "r"(a[3]), "r"(b[0]), "r"(b[1]));
}

__device__ __forceinline__ void cp_async16(void* smem, const void* gmem) {
    uint32_t s = (uint32_t)__cvta_generic_to_shared(smem);
    asm volatile("cp.async.cg.shared.global [%0], [%1], 16;\n" :: "r"(s), "l"(gmem));
}
#define CP_COMMIT() asm volatile("cp.async.commit_group;\n" ::: "memory")
#define CP_WAIT1()  asm volatile("cp.async.wait_group 1;\n" ::: "memory")

// ---------------------------------------------------------------------------
// NT GEMM (3xTF32 tensor cores): C[m,n] = alpha * sum_k A[m,k]*B[n,k] + bias[n]
// A:[M,K] row-major, B:[N,K] row-major. M%128==0, N%128==0, K%16==0.
// ---------------------------------------------------------------------------
__global__ __launch_bounds__(256)
void gemm_nt_mma(const float* __restrict__ A, const float* __restrict__ B,
                 const float* __restrict__ bias, float* __restrict__ C,
                 int M, int N, int K, float alpha,
                 long long sA, long long sB, long long sC)
{
    A += (long long)blockIdx.z * sA;
    B += (long long)blockIdx.z * sB;
    C += (long long)blockIdx.z * sC;

    __shared__ float As[2][BM * AST];
    __shared__ float Bs[2][BN * AST];

    const int tid  = threadIdx.x;
    const int lane = tid & 31;
    const int wid  = tid >> 5;
    const int warp_m = wid >> 2;   // 0..1  (64 rows each)
    const int warp_n = wid & 3;    // 0..3  (32 cols each)

    const int m0 = blockIdx.y * BM;
    const int n0 = blockIdx.x * BN;

    const int ld_m  = tid >> 2;         // 0..63 (with +64 on second op)
    const int ld_kc = (tid & 3) * 4;    // 0,4,8,12

    const float* Abase = A + (long long)m0 * K;
    const float* Bbase = B + (long long)n0 * K;

    const int nt = K / BK;

    float acc[4][4][4];
    #pragma unroll
    for (int i = 0; i < 4; i++)
        #pragma unroll
        for (int j = 0; j < 4; j++)
            #pragma unroll
            for (int r = 0; r < 4; r++) acc[i][j][r] = 0.f;

    // prologue: stage 0 <- tile 0
    {
        #pragma unroll
        for (int j = 0; j < 2; j++) {
            int m = ld_m + j * 64;
            cp_async16(&As[0][m * AST + ld_kc], Abase + (long long)m * K + ld_kc);
            cp_async16(&Bs[0][m * AST + ld_kc], Bbase + (long long)m * K + ld_kc);
        }
        CP_COMMIT();
    }

    const int r = lane >> 2;   // group id
    const int c = lane & 3;    // thread in group

    for (int t = 0; t < nt; ++t) {
        if (t + 1 < nt) {
            int s = (t + 1) & 1;
            const float* Ag = Abase + (long long)(t + 1) * BK;
            const float* Bg = Bbase + (long long)(t + 1) * BK;
            #pragma unroll
            for (int j = 0; j < 2; j++) {
                int m = ld_m + j * 64;
                cp_async16(&As[s][m * AST + ld_kc], Ag + (long long)m * K + ld_kc);
                cp_async16(&Bs[s][m * AST + ld_kc], Bg + (long long)m * K + ld_kc);
            }
        }
        CP_COMMIT();
        CP_WAIT1();
        __syncthreads();

        const float* as = As[t & 1];
        const float* bs = Bs[t & 1];

        #pragma unroll
        for (int ks = 0; ks < 2; ks++) {
            uint32_t afh[4][4], afl[4][4], bfh[4][2], bfl[4][2];
            #pragma unroll
            for (int mt = 0; mt < 4; mt++) {
                int row = warp_m * 64 + mt * 16 + r;
                split_tf32(as[row * AST + ks * 8 + c],           afh[mt][0], afl[mt][0]);
                split_tf32(as[(row + 8) * AST + ks * 8 + c],     afh[mt][1], afl[mt][1]);
                split_tf32(as[row * AST + ks * 8 + c + 4],       afh[mt][2], afl[mt][2]);
                split_tf32(as[(row + 8) * AST + ks * 8 + c + 4], afh[mt][3], afl[mt][3]);
            }
            #pragma unroll
            for (int ntt = 0; ntt < 4; ntt++) {
                int col = warp_n * 32 + ntt * 8 + r;
                split_tf32(bs[col * AST + ks * 8 + c],     bfh[ntt][0], bfl[ntt][0]);
                split_tf32(bs[col * AST + ks * 8 + c + 4], bfh[ntt][1], bfl[ntt][1]);
            }
            #pragma unroll
            for (int mt = 0; mt < 4; mt++)
                #pragma unroll
                for (int ntt = 0; ntt < 4; ntt++) {
                    mma_tf32(acc[mt][ntt], afl[mt], bfh[ntt]);
                    mma_tf32(acc[mt][ntt], afh[mt], bfl[ntt]);
                    mma_tf32(acc[mt][ntt], afh[mt], bfh[ntt]);
                }
        }
        __syncthreads();
    }

    // epilogue
    #pragma unroll
    for (int mt = 0; mt < 4; mt++) {
        int row = m0 + warp_m * 64 + mt * 16 + r;
        #pragma unroll
        for (int ntt = 0; ntt < 4; ntt++) {
            int col = n0 + warp_n * 32 + ntt * 8 + c * 2;
            float b0 = 0.f, b1 = 0.f;
            if (bias) { b0 = bias[col]; b1 = bias[col + 1]; }
            float2 v0 = make_float2(alpha * acc[mt][ntt][0] + b0,
                                    alpha * acc[mt][ntt][1] + b1);
            float2 v1 = make_float2(alpha * acc[mt][ntt][2] + b0,
                                    alpha * acc[mt][ntt][3] + b1);
            *reinterpret_cast<float2*>(C + (long long)row * N + col) = v0;
            *reinterpret_cast<float2*>(C + (long long)(row + 8) * N + col) = v1;
        }
    }
}

// ---------------------------------------------------------------------------
// NN GEMM (3xTF32 tensor cores): C[m,n] = sum_k A[m,k]*B[k,n]
// A:[M,K] row-major, B:[K,N] row-major.
// ---------------------------------------------------------------------------
__global__ __launch_bounds__(256)
void gemm_nn_mma(const float* __restrict__ A, const float* __restrict__ B,
                 float* __restrict__ C,
                 int M, int N, int K,
                 long long sA, long long sB, long long sC)
{
    A += (long long)blockIdx.z * sA;
    B += (long long)blockIdx.z * sB;
    C += (long long)blockIdx.z * sC;

    __shared__ float As[2][BM * AST];
    __shared__ float Bs[2][BK * BKST];

    const int tid  = threadIdx.x;
    const int lane = tid & 31;
    const int wid  = tid >> 5;
    const int warp_m = wid >> 2;
    const int warp_n = wid & 3;

    const int m0 = blockIdx.y * BM;
    const int n0 = blockIdx.x * BN;

    const int ld_m  = tid >> 2;
    const int ld_kc = (tid & 3) * 4;
    const int ld_bk = tid >> 5;          // 0..7 (+8 second op)
    const int ld_bn = (tid & 31) * 4;    // 0..124

    const float* Abase = A + (long long)m0 * K;
    const float* Bbase = B + n0;

    const int nt = K / BK;

    float acc[4][4][4];
    #pragma unroll
    for (int i = 0; i < 4; i++)
        #pragma unroll
        for (int j = 0; j < 4; j++)
            #pragma unroll
            for (int r = 0; r < 4; r++) acc[i][j][r] = 0.f;

    {
        #pragma unroll
        for (int j = 0; j < 2; j++) {
            int m = ld_m + j * 64;
            cp_async16(&As[0][m * AST + ld_kc], Abase + (long long)m * K + ld_kc);
            int k = ld_bk + j * 8;
            cp_async16(&Bs[0][k * BKST + ld_bn], Bbase + (long long)k * N + ld_bn);
        }
        CP_COMMIT();
    }

    const int r = lane >> 2;
    const int c = lane & 3;

    for (int t = 0; t < nt; ++t) {
        if (t + 1 < nt) {
            int s = (t + 1) & 1;
            const float* Ag = Abase + (long long)(t + 1) * BK;
            const float* Bg = Bbase + (long long)(t + 1) * BK * N;
            #pragma unroll
            for (int j = 0; j < 2; j++) {
                int m = ld_m + j * 64;
                cp_async16(&As[s][m * AST + ld_kc], Ag + (long long)m * K + ld_kc);
                int k = ld_bk + j * 8;
                cp_async16(&Bs[s][k * BKST + ld_bn], Bg + (long long)k * N + ld_bn);
            }
        }
        CP_COMMIT();
        CP_WAIT1();
        __syncthreads();

        const float* as = As[t & 1];
        const float* bs = Bs[t & 1];

        #pragma unroll
        for (int ks = 0; ks < 2; ks++) {
            uint32_t afh[4][4], afl[4][4], bfh[4][2], bfl[4][2];
            #pragma unroll
            for (int mt = 0; mt < 4; mt++) {
                int row = warp_m * 64 + mt * 16 + r;
                split_tf32(as[row * AST + ks * 8 + c],           afh[mt][0], afl[mt][0]);
                split_tf32(as[(row + 8) * AST + ks * 8 + c],     afh[mt][1], afl[mt][1]);
                split_tf32(as[row * AST + ks * 8 + c + 4],       afh[mt][2], afl[mt][2]);
                split_tf32(as[(row + 8) * AST + ks * 8 + c + 4], afh[mt][3], afl[mt][3]);
            }
            #pragma unroll
            for (int ntt = 0; ntt < 4; ntt++) {
                int col = warp_n * 32 + ntt * 8 + r;
                split_tf32(bs[(ks * 8 + c) * BKST + col],     bfh[ntt][0], bfl[ntt][0]);
                split_tf32(bs[(ks * 8 + c + 4) * BKST + col], bfh[ntt][1], bfl[ntt][1]);
            }
            #pragma unroll
            for (int mt = 0; mt < 4; mt++)
                #pragma unroll
                for (int ntt = 0; ntt < 4; ntt++) {
                    mma_tf32(acc[mt][ntt], afl[mt], bfh[ntt]);
                    mma_tf32(acc[mt][ntt], afh[mt], bfl[ntt]);
                    mma_tf32(acc[mt][ntt], afh[mt], bfh[ntt]);
                }
        }
        __syncthreads();
    }

    #pragma unroll
    for (int mt = 0; mt < 4; mt++) {
        int row = m0 + warp_m * 64 + mt * 16 + r;
        #pragma unroll
        for (int ntt = 0; ntt < 4; ntt++) {
            int col = n0 + warp_n * 32 + ntt * 8 + c * 2;
            float2 v0 = make_float2(acc[mt][ntt][0], acc[mt][ntt][1]);
            float2 v1 = make_float2(acc[mt][ntt][2], acc[mt][ntt][3]);
            *reinterpret_cast<float2*>(C + (long long)row * N + col) = v0;
            *reinterpret_cast<float2*>(C + (long long)(row + 8) * N + col) = v1;
        }
    }
}

// ---------------------------------------------------------------------------
// Row softmax over 4096 columns, one block (256 threads) per row.
// ---------------------------------------------------------------------------
__device__ __forceinline__ float warp_max(float v) {
    #pragma unroll
    for (int o = 16; o > 0; o >>= 1) v = fmaxf(v, __shfl_xor_sync(0xffffffffu, v, o));
    return v;
}
__device__ __forceinline__ float warp_sum(float v) {
    #pragma unroll
    for (int o = 16; o > 0; o >>= 1) v += __shfl_xor_sync(0xffffffffu, v, o);
    return v;
}

__global__ __launch_bounds__(256)
void softmax_rows(float* __restrict__ S)
{
    const int tid = threadIdx.x;
    float* r = S + (size_t)blockIdx.x * SDIM;

    __shared__ float red[8];

    float v[16];
    float mx = -1e30f;
    #pragma unroll
    for (int i = 0; i < 16; i++) {
        v[i] = r[tid + i * 256];
        mx = fmaxf(mx, v[i]);
    }
    mx = warp_max(mx);
    if ((tid & 31) == 0) red[tid >> 5] = mx;
    __syncthreads();
    {
        float t = (tid < 8) ? red[tid] : -1e30f;
        t = warp_max(t);
        if (tid == 0) red[0] = t;
    }
    __syncthreads();
    mx = red[0];
    __syncthreads();

    float sum = 0.f;
    #pragma unroll
    for (int i = 0; i < 16; i++) {
        v[i] = __expf(v[i] - mx);
        sum += v[i];
    }
    sum = warp_sum(sum);
    if ((tid & 31) == 0) red[tid >> 5] = sum;
    __syncthreads();
    {
        float t = (tid < 8) ? red[tid] : 0.f;
        t = warp_sum(t);
        if (tid == 0) red[0] = t;
    }
    __syncthreads();
    const float inv = 1.f / red[0];

    #pragma unroll
    for (int i = 0; i < 16; i++)
        r[tid + i * 256] = v[i] * inv;
}

// ---------------------------------------------------------------------------
// Launch
// ---------------------------------------------------------------------------
extern "C" void kernel_launch(void* const* d_in, const int* in_sizes, int n_in,
                              void* d_out, int out_size)
{
    const float* x  = (const float*)d_in[0];
    const float* Wq = (const float*)d_in[1];
    const float* bq = (const float*)d_in[2];
    const float* Wk = (const float*)d_in[3];
    const float* bk = (const float*)d_in[4];
    const float* Wv = (const float*)d_in[5];
    const float* bv = (const float*)d_in[6];
    const float* Wo = (const float*)d_in[7];
    const float* bo = (const float*)d_in[8];
    float* out = (float*)d_out;

    const dim3 blk(256);

    // QKV projections: [8192,1024]
    dim3 gproj(HDIM / BN, MDIM / BM, 1);   // (8, 64)
    gemm_nt_mma<<<gproj, blk>>>(x, Wq, bq, g_q, MDIM, HDIM, HDIM, 1.f, 0, 0, 0);
    gemm_nt_mma<<<gproj, blk>>>(x, Wk, bk, g_k, MDIM, HDIM, HDIM, 1.f, 0, 0, 0);
    gemm_nt_mma<<<gproj, blk>>>(x, Wv, bv, g_v, MDIM, HDIM, HDIM, 1.f, 0, 0, 0);

    // scores = Q K^T / 8  (per batch)
    dim3 gsc(SDIM / BN, SDIM / BM, BDIM);  // (32, 32, 2)
    gemm_nt_mma<<<gsc, blk>>>(g_q, g_k, nullptr, g_s, SDIM, SDIM, HDIM, 0.125f,
                              (long long)SDIM * HDIM, (long long)SDIM * HDIM,
                              (long long)SDIM * SDIM);

    // softmax rows
    softmax_rows<<<BDIM * SDIM, blk>>>(g_s);

    // attn = P V  (per batch)
    dim3 gpv(HDIM / BN, SDIM / BM, BDIM);  // (8, 32, 2)
    gemm_nn_mma<<<gpv, blk>>>(g_s, g_v, g_attn, SDIM, HDIM, SDIM,
                              (long long)SDIM * SDIM, (long long)SDIM * HDIM,
                              (long long)SDIM * HDIM);

    // out = attn Wo^T + bo
    gemm_nt_mma<<<gproj, blk>>>(g_attn, Wo, bo, out, MDIM, HDIM, HDIM, 1.f, 0, 0, 0);
}